// round 15
// baseline (speedup 1.0000x reference)
#include <cuda_runtime.h>
#include <cstdint>

// Problem constants
#define NN 50000
#define DD 128
#define EE 800000
#define ND (NN*DD)
#define TB 256
#define K1 25000
#define K2 12500
#define FGRID 888                // 6 blocks/SM x 148 SMs (co-residency enforced)
#define SCAN_GRID 64
#define GEMM_TB 1024
#define GEMM_SMEM (128*128*4)    // 64KB dynamic

// ----------------------------------------------------------------------------
// Device scratch (allocation-free: __device__ globals)
// ----------------------------------------------------------------------------
__device__ float g_h[ND];
__device__ float g_t[ND];
__device__ float g_g[ND];
__device__ float g_xx[ND];
__device__ float g_d0[ND];
__device__ float g_d1[ND];
__device__ int   g_nbrr[EE];
__device__ int   g_nbrc[EE];
__device__ int   g_ownr[EE];
__device__ int   g_ownc[EE];
__device__ float g_ecc0[EE];
__device__ float g_ecc1[EE];
__device__ float g_ecc2[EE];
__device__ float g_ctc0[EE];
__device__ float g_ctc1[EE];
__device__ float g_ctr0[EE];
__device__ float g_ctr1[EE];
// packed node state: x=nm, y=normed, z=dis, w=aggr
__device__ float4 g_node[NN];
__device__ float g_dsum[NN];     // deg-sum, then inv = nm/aggr
__device__ float g_asum[NN];
__device__ float g_w[NN];
__device__ float g_score[NN];
__device__ float g_s[NN];
__device__ unsigned int g_hist[3 * 65536];   // triple-buffered radix histograms
__device__ unsigned int g_part2[SCAN_GRID];
__device__ unsigned long long g_prefix;
__device__ int g_k;
__device__ float g_pinv[2];
__device__ int g_cntr[NN];
__device__ int g_cntc[NN];
__device__ int g_offr[NN + 1];
__device__ int g_offc[NN + 1];
__device__ int g_curr[NN];
__device__ int g_curc[NN];
__device__ int g_act0[NN];
__device__ int g_act1[NN];
__device__ int g_acnt0;
__device__ int g_acnt1;
// software grid barrier — self-cleaning across graph replays; NEVER reset.
__device__ int g_barcnt = 0;
__device__ unsigned g_bargen = 0u;

// ----------------------------------------------------------------------------
// f32x2 packed-FMA helpers
// ----------------------------------------------------------------------------
__device__ __forceinline__ unsigned long long fma2(unsigned long long a,
                                                   unsigned long long b,
                                                   unsigned long long c) {
    unsigned long long d;
    asm("fma.rn.f32x2 %0, %1, %2, %3;" : "=l"(d) : "l"(a), "l"(b), "l"(c));
    return d;
}
__device__ __forceinline__ unsigned long long pack2(float x) {
    unsigned long long d;
    asm("mov.b64 %0, {%1, %1};" : "=l"(d) : "f"(x));
    return d;
}
__device__ __forceinline__ float2 unpack2(unsigned long long v) {
    float2 r;
    asm("mov.b64 {%0, %1}, %2;" : "=f"(r.x), "=f"(r.y) : "l"(v));
    return r;
}

// ----------------------------------------------------------------------------
// Software grid barrier (all blocks co-resident)
// ----------------------------------------------------------------------------
__device__ __forceinline__ void gridbar() {
    __syncthreads();
    if (threadIdx.x == 0) {
        unsigned gen = *((volatile unsigned*)&g_bargen);
        __threadfence();
        int ticket = atomicAdd(&g_barcnt, 1);
        if (ticket == (int)gridDim.x - 1) {
            g_barcnt = 0;
            __threadfence();
            atomicAdd(&g_bargen, 1u);
        } else {
            while (*((volatile unsigned*)&g_bargen) == gen) {}
        }
        __threadfence();
    }
    __syncthreads();
}

// ----------------------------------------------------------------------------
// Device helper: grid-stride CSR gather (warp per node)
// ----------------------------------------------------------------------------
template<bool SKIP, bool ADDIN, bool SCORE>
__device__ __forceinline__ void dev_gather(
    const float* __restrict__ src, float* __restrict__ dst,
    const int* __restrict__ off, const int* __restrict__ nbr,
    const float* __restrict__ cf, const float* __restrict__ addin,
    const float* __restrict__ pv, int lvl,
    const int* __restrict__ list, int nlist) {
    int lane = threadIdx.x & 31;
    int w0 = (blockIdx.x * blockDim.x + threadIdx.x) >> 5;
    int nwt = (gridDim.x * blockDim.x) >> 5;
    for (int w = w0; w < nlist; w += nwt) {
        int v = list ? list[w] : w;
        int s = off[v], e = off[v + 1];
        float ax = 0.f, ay = 0.f, az = 0.f, aw = 0.f;
        int i = s;
        for (; i + 4 <= e; i += 4) {
            int   n0 = nbr[i],   n1 = nbr[i+1],   n2 = nbr[i+2],   n3 = nbr[i+3];
            float w0_ = cf[i],   w1_ = cf[i+1],   w2_ = cf[i+2],   w3_ = cf[i+3];
            if (!SKIP || w0_ != 0.f) {
                float4 t = ((const float4*)src)[(size_t)n0 * 32 + lane];
                ax = fmaf(w0_, t.x, ax); ay = fmaf(w0_, t.y, ay);
                az = fmaf(w0_, t.z, az); aw = fmaf(w0_, t.w, aw);
            }
            if (!SKIP || w1_ != 0.f) {
                float4 t = ((const float4*)src)[(size_t)n1 * 32 + lane];
                ax = fmaf(w1_, t.x, ax); ay = fmaf(w1_, t.y, ay);
                az = fmaf(w1_, t.z, az); aw = fmaf(w1_, t.w, aw);
            }
            if (!SKIP || w2_ != 0.f) {
                float4 t = ((const float4*)src)[(size_t)n2 * 32 + lane];
                ax = fmaf(w2_, t.x, ax); ay = fmaf(w2_, t.y, ay);
                az = fmaf(w2_, t.z, az); aw = fmaf(w2_, t.w, aw);
            }
            if (!SKIP || w3_ != 0.f) {
                float4 t = ((const float4*)src)[(size_t)n3 * 32 + lane];
                ax = fmaf(w3_, t.x, ax); ay = fmaf(w3_, t.y, ay);
                az = fmaf(w3_, t.z, az); aw = fmaf(w3_, t.w, aw);
            }
        }
        for (; i < e; i++) {
            int n = nbr[i]; float wv = cf[i];
            if (!SKIP || wv != 0.f) {
                float4 t = ((const float4*)src)[(size_t)n * 32 + lane];
                ax = fmaf(wv, t.x, ax); ay = fmaf(wv, t.y, ay);
                az = fmaf(wv, t.z, az); aw = fmaf(wv, t.w, aw);
            }
        }
        if (ADDIN) {
            float4 a = ((const float4*)addin)[(size_t)v * 32 + lane];
            ax += a.x; ay += a.y; az += a.z; aw += a.w;
        }
        ((float4*)dst)[(size_t)v * 32 + lane] = make_float4(ax, ay, az, aw);
        if (SCORE) {
            float4 p = ((const float4*)pv)[lane];
            float sdot = ax*p.x + ay*p.y + az*p.z + aw*p.w;
            #pragma unroll
            for (int o = 16; o; o >>= 1) sdot += __shfl_xor_sync(0xffffffffu, sdot, o);
            if (lane == 0) g_score[v] = sdot * g_pinv[lvl];
        }
    }
}

// ----------------------------------------------------------------------------
// Device helper: edge-parallel prep (assumes dsum/asum pre-zeroed)
// ----------------------------------------------------------------------------
__device__ void dev_prep(const int* __restrict__ ei,
                         float* __restrict__ ecc,
                         float* __restrict__ ctc,
                         float* __restrict__ ctr) {
    int gid = blockIdx.x * blockDim.x + threadIdx.x;
    int gs = gridDim.x * blockDim.x;
    // B: deg-sum
    for (int e = gid; e < EE; e += gs) {
        int r = ei[e], c = ei[EE + e];
        float nmc = __ldg(&g_node[c].x);
        if (nmc != 0.f) atomicAdd(&g_dsum[r], nmc);
    }
    gridbar();
    // C: derive dis/normed
    for (int v = gid; v < NN; v += gs) {
        float4 n4 = g_node[v];
        float d = n4.x * g_dsum[v];
        if (d > 0.f) { n4.z = rsqrtf(d); n4.y = g_w[v] / d; }
        else         { n4.z = 0.f; n4.y = 0.f; }
        g_node[v] = n4;
    }
    gridbar();
    if (ctc || ctr) {
        // D: aggr-sum
        for (int e = gid; e < EE; e += gs) {
            int r = ei[e], c = ei[EE + e];
            float2 rn = *(const float2*)&g_node[r];
            float v = rn.y * rn.x;
            if (v != 0.f) atomicAdd(&g_asum[c], v);
        }
        gridbar();
        // E: aggr + inv (inv stored in dsum)
        for (int v = gid; v < NN; v += gs) {
            float4 n4 = g_node[v];
            float aggr = fmaf(n4.x, g_asum[v], 1e-12f);
            n4.w = aggr;
            g_node[v] = n4;
            g_dsum[v] = n4.x / aggr;
        }
        gridbar();
    }
    // F: coefficient writes
    for (int i = gid; i < EE; i += gs) {
        int c = g_ownc[i];
        int r = g_nbrc[i];
        float4 nr = g_node[r];
        ecc[i] = nr.z * __ldg(&g_node[c].z);
        if (ctc) ctc[i] = nr.y * nr.x * g_dsum[c];
        if (ctr) {
            int rr = g_ownr[i];
            int cc = g_nbrr[i];
            float2 rn = *(const float2*)&g_node[rr];
            ctr[i] = rn.y * rn.x * g_dsum[cc];
        }
    }
}

// ----------------------------------------------------------------------------
// Launch 1: setup — init, edge hist, scans, CSR fill, level-0 prep
// ----------------------------------------------------------------------------
__device__ void scan256(const int* __restrict__ cnt, int* __restrict__ off,
                        int* __restrict__ cur, int* part) {
    const int PER = 196;
    int t = threadIdx.x;
    int base = t * PER;
    int s = 0;
    for (int i = 0; i < PER; i++) { int idx = base + i; if (idx < NN) s += cnt[idx]; }
    part[t] = s;
    __syncthreads();
    if (t == 0) {
        int acc = 0;
        for (int i = 0; i < 256; i++) { int v = part[i]; part[i] = acc; acc += v; }
        off[NN] = acc;
    }
    __syncthreads();
    int run = part[t];
    for (int i = 0; i < PER; i++) {
        int idx = base + i;
        if (idx < NN) { off[idx] = run; cur[idx] = run; run += cnt[idx]; }
    }
}

__global__ void __launch_bounds__(TB, 6) k_setup(const float* __restrict__ pvec,
                                                 const int* __restrict__ ei) {
    __shared__ int part[256];
    int gid = blockIdx.x * blockDim.x + threadIdx.x;
    int gs = gridDim.x * blockDim.x;
    // init
    for (int j = gid; j < 3 * 65536; j += gs) g_hist[j] = 0u;
    for (int v = gid; v < NN; v += gs) {
        g_node[v] = make_float4(1.f, 0.f, 0.f, 0.f);
        g_w[v] = 1.0f;
        g_cntr[v] = 0; g_cntc[v] = 0;
        g_dsum[v] = 0.f; g_asum[v] = 0.f;
    }
    if (gid == 0) { g_acnt0 = 0; g_acnt1 = 0; }
    if (blockIdx.x == 0 && threadIdx.x < 64) {
        int l = threadIdx.x >> 5, lane = threadIdx.x & 31;
        float4 p = ((const float4*)(pvec + l * DD))[lane];
        float s = p.x*p.x + p.y*p.y + p.z*p.z + p.w*p.w;
        #pragma unroll
        for (int o = 16; o; o >>= 1) s += __shfl_xor_sync(0xffffffffu, s, o);
        if (lane == 0) g_pinv[l] = rsqrtf(s);
    }
    gridbar();
    // edge degree histogram
    for (int e = gid; e < EE; e += gs) {
        atomicAdd(&g_cntr[ei[e]], 1);
        atomicAdd(&g_cntc[ei[EE + e]], 1);
    }
    gridbar();
    if (blockIdx.x == 0) {
        scan256(g_cntr, g_offr, g_curr, part);
        __syncthreads();
        scan256(g_cntc, g_offc, g_curc, part);
    }
    gridbar();
    for (int e = gid; e < EE; e += gs) {
        int r = ei[e], c = ei[EE + e];
        int pr = atomicAdd(&g_curr[r], 1);
        g_nbrr[pr] = c;
        g_ownr[pr] = r;
        int pc = atomicAdd(&g_curc[c], 1);
        g_nbrc[pc] = r;
        g_ownc[pc] = c;
    }
    gridbar();
    dev_prep(ei, g_ecc0, g_ctc0, g_ctr0);
}

// ----------------------------------------------------------------------------
// k_pool: gather(ecc) -> gather(ct)+score -> fused top-k -> apply/compact
// ----------------------------------------------------------------------------
template<bool SKIP>
__global__ void __launch_bounds__(TB, 6) k_pool(
    const float* __restrict__ src1, float* __restrict__ dst1,
    const float* __restrict__ ecc,
    float* __restrict__ dstH, const float* __restrict__ ct,
    const float* __restrict__ pv, int lvl,
    const int* __restrict__ list2, int n2,
    int kval, int* __restrict__ act, int* __restrict__ acnt) {
    __shared__ unsigned red[256];
    __shared__ unsigned sf[256];
    __shared__ int sel_b;
    __shared__ unsigned sel_cum;
    int gid = blockIdx.x * blockDim.x + threadIdx.x;
    int gs = gridDim.x * blockDim.x;
    int t = threadIdx.x;

    dev_gather<SKIP, false, false>(src1, dst1, g_offc, g_nbrc, ecc,
                                   nullptr, nullptr, 0, nullptr, NN);
    gridbar();
    dev_gather<SKIP, false, true>(dst1, dstH, g_offc, g_nbrc, ct,
                                  nullptr, pv, lvl, list2, n2);
    gridbar();

    // ---- fused top-k (3x16-bit radix, triple-buffered hist) ----
    bool valid = (gid < NN);
    unsigned long long key = 0ull;
    if (gid == 0) { g_prefix = 0ull; g_k = kval; }
    if (valid) {
        float s = (g_node[gid].x > 0.f) ? g_score[gid] : __int_as_float(0xff800000);
        unsigned u = __float_as_uint(s);
        u = (u & 0x80000000u) ? ~u : (u | 0x80000000u);
        key = ((unsigned long long)u << 16) |
              (unsigned long long)(65535u - (unsigned)gid);
        atomicAdd(&g_hist[(unsigned)(key >> 32)], 1u);
    }
    gridbar();

    for (int p = 0; p < 3; p++) {
        unsigned* H = g_hist + p * 65536;
        if (blockIdx.x < SCAN_GRID) {
            int base = blockIdx.x * 1024;
            unsigned s = 0;
            #pragma unroll
            for (int i = 0; i < 4; i++) s += H[base + t + i * 256];
            red[t] = s;
            __syncthreads();
            for (int o = 128; o; o >>= 1) { if (t < o) red[t] += red[t + o]; __syncthreads(); }
            if (t == 0) g_part2[blockIdx.x] = red[0];
        }
        gridbar();
        if (blockIdx.x == 0) {
            if (t == 0) {
                unsigned k = (unsigned)g_k;
                unsigned cum = 0;
                int bb = 0;
                for (bb = SCAN_GRID - 1; bb > 0; bb--) {
                    unsigned pp = g_part2[bb];
                    if (cum + pp >= k) break;
                    cum += pp;
                }
                sel_b = bb;
                sel_cum = cum;
            }
            __syncthreads();
            int bb = sel_b;
            unsigned kk = (unsigned)g_k - sel_cum;
            int sbase = bb * 1024 + t * 4;
            unsigned h0 = H[sbase], h1 = H[sbase + 1];
            unsigned h2 = H[sbase + 2], h3 = H[sbase + 3];
            sf[t] = h0 + h1 + h2 + h3;
            __syncthreads();
            for (int off = 1; off < 256; off <<= 1) {
                unsigned v = sf[t];
                unsigned ad = (t + off < 256) ? sf[t + off] : 0u;
                __syncthreads();
                sf[t] = v + ad;
                __syncthreads();
            }
            unsigned above = (t < 255) ? sf[t + 1] : 0u;
            if (above < kk && sf[t] >= kk) {
                unsigned cum = above;
                int d = sbase;
                if (cum + h3 >= kk)               { d = sbase + 3; }
                else if (cum + h3 + h2 >= kk)     { cum += h3; d = sbase + 2; }
                else if (cum + h3 + h2 + h1 >= kk){ cum += h3 + h2; d = sbase + 1; }
                else                              { cum += h3 + h2 + h1; d = sbase; }
                g_prefix = (g_prefix << 16) | (unsigned long long)(unsigned)d;
                g_k = (int)(kk - cum);
            }
        }
        gridbar();
        if (p < 2) {
            int pp = p + 1;
            if (valid && ((key >> (48 - 16 * pp)) == g_prefix)) {
                unsigned d = (unsigned)(key >> (32 - 16 * pp)) & 0xFFFFu;
                atomicAdd(&g_hist[pp * 65536 + d], 1u);
            }
            gridbar();
        }
    }

    // apply + compact + scratch zero
    if (valid) {
        bool kept = (key >= g_prefix);
        float4 n4 = g_node[gid];
        g_w[gid] = kept ? n4.w : 0.f;
        g_s[gid] = kept ? tanhf(g_score[gid]) : 0.f;
        n4.x = kept ? 1.f : 0.f;
        g_node[gid] = n4;
        if (kept) {
            int slot = atomicAdd(acnt, 1);
            act[slot] = gid;
        }
        g_dsum[gid] = 0.f;
        g_asum[gid] = 0.f;
    }
    for (int i = gid; i < 3 * 65536; i += gs) g_hist[i] = 0u;
}

// ----------------------------------------------------------------------------
// k_prepgather: per-level prep then compacted gather
// ----------------------------------------------------------------------------
__global__ void __launch_bounds__(TB, 6) k_prepgather(
    const int* __restrict__ ei,
    float* __restrict__ ecc, float* __restrict__ ctc, float* __restrict__ ctr,
    const float* __restrict__ src, float* __restrict__ dst,
    const int* __restrict__ list, int n) {
    dev_prep(ei, ecc, ctc, ctr);
    gridbar();
    dev_gather<true, false, false>(src, dst, g_offc, g_nbrc, ecc,
                                   nullptr, nullptr, 0, list, n);
}

// ----------------------------------------------------------------------------
// k_2gather: two dependent gathers in one launch
// ----------------------------------------------------------------------------
template<bool S1, bool A1, bool S2>
__global__ void __launch_bounds__(TB, 6) k_2gather(
    const float* __restrict__ src1, float* __restrict__ dst1,
    const int* __restrict__ off1, const int* __restrict__ nbr1,
    const float* __restrict__ cf1, const float* __restrict__ add1,
    const int* __restrict__ l1, int n1,
    float* __restrict__ dst2,
    const int* __restrict__ off2, const int* __restrict__ nbr2,
    const float* __restrict__ cf2,
    const int* __restrict__ l2, int n2) {
    if (A1)
        dev_gather<S1, true, false>(src1, dst1, off1, nbr1, cf1, add1,
                                    nullptr, 0, l1, n1);
    else
        dev_gather<S1, false, false>(src1, dst1, off1, nbr1, cf1, nullptr,
                                     nullptr, 0, l1, n1);
    gridbar();
    dev_gather<S2, false, false>(dst1, dst2, off2, nbr2, cf2, nullptr,
                                 nullptr, 0, l2, n2);
}

// ----------------------------------------------------------------------------
// Standalone CSR gather (full grid, max occupancy) — for unfusable gathers
// ----------------------------------------------------------------------------
template<bool SKIP, bool ADDIN>
__global__ void __launch_bounds__(256) k_gather_t(
    const float* __restrict__ src, float* __restrict__ dst,
    const int* __restrict__ off, const int* __restrict__ nbr,
    const float* __restrict__ cf, const float* __restrict__ addin,
    const int* __restrict__ list, int nlist) {
    int wid = (blockIdx.x * blockDim.x + threadIdx.x) >> 5;
    if (wid >= nlist) return;
    int v = list ? list[wid] : wid;
    int lane = threadIdx.x & 31;
    int s = off[v], e = off[v + 1];
    float ax = 0.f, ay = 0.f, az = 0.f, aw = 0.f;
    int i = s;
    if (!SKIP) {
        int e8 = s + ((e - s) & ~7);
        for (; i < e8; i += 8) {
            int n[8]; float w[8]; float4 t[8];
            #pragma unroll
            for (int u = 0; u < 8; u++) { n[u] = nbr[i + u]; w[u] = cf[i + u]; }
            #pragma unroll
            for (int u = 0; u < 8; u++)
                t[u] = ((const float4*)src)[(size_t)n[u] * 32 + lane];
            #pragma unroll
            for (int u = 0; u < 8; u++) {
                ax = fmaf(w[u], t[u].x, ax); ay = fmaf(w[u], t[u].y, ay);
                az = fmaf(w[u], t[u].z, az); aw = fmaf(w[u], t[u].w, aw);
            }
        }
    } else {
        for (; i + 4 <= e; i += 4) {
            int   n0 = nbr[i],   n1 = nbr[i+1],   n2 = nbr[i+2],   n3 = nbr[i+3];
            float w0 = cf[i],    w1 = cf[i+1],    w2 = cf[i+2],    w3 = cf[i+3];
            if (w0 != 0.f) {
                float4 t = ((const float4*)src)[(size_t)n0 * 32 + lane];
                ax = fmaf(w0, t.x, ax); ay = fmaf(w0, t.y, ay);
                az = fmaf(w0, t.z, az); aw = fmaf(w0, t.w, aw);
            }
            if (w1 != 0.f) {
                float4 t = ((const float4*)src)[(size_t)n1 * 32 + lane];
                ax = fmaf(w1, t.x, ax); ay = fmaf(w1, t.y, ay);
                az = fmaf(w1, t.z, az); aw = fmaf(w1, t.w, aw);
            }
            if (w2 != 0.f) {
                float4 t = ((const float4*)src)[(size_t)n2 * 32 + lane];
                ax = fmaf(w2, t.x, ax); ay = fmaf(w2, t.y, ay);
                az = fmaf(w2, t.z, az); aw = fmaf(w2, t.w, aw);
            }
            if (w3 != 0.f) {
                float4 t = ((const float4*)src)[(size_t)n3 * 32 + lane];
                ax = fmaf(w3, t.x, ax); ay = fmaf(w3, t.y, ay);
                az = fmaf(w3, t.z, az); aw = fmaf(w3, t.w, aw);
            }
        }
    }
    for (; i < e; i++) {
        int n = nbr[i]; float w = cf[i];
        if (!SKIP || w != 0.f) {
            float4 t = ((const float4*)src)[(size_t)n * 32 + lane];
            ax = fmaf(w, t.x, ax); ay = fmaf(w, t.y, ay);
            az = fmaf(w, t.z, az); aw = fmaf(w, t.w, aw);
        }
    }
    if (ADDIN) {
        float4 a = ((const float4*)addin)[(size_t)v * 32 + lane];
        ax += a.x; ay += a.y; az += a.z; aw += a.w;
    }
    ((float4*)dst)[(size_t)v * 32 + lane] = make_float4(ax, ay, az, aw);
}

// ----------------------------------------------------------------------------
// Dense GEMM v4: block = 128 rows x 128 cols, full W in 64KB dynamic smem,
// 1024 threads, 2x8/thread, A broadcast LDG (read ONCE), FFMA2,
// scale in epilogue. grid = ceil(m/128).
// ----------------------------------------------------------------------------
__global__ void __launch_bounds__(GEMM_TB) k_gemm(const float* __restrict__ A,
                                                  const float* __restrict__ W,
                                                  const float* __restrict__ bias,
                                                  float* __restrict__ C,
                                                  const float* __restrict__ scale,
                                                  const int* __restrict__ rowidx,
                                                  int m) {
    extern __shared__ float sW[];          // [128][128]
    const int tid = threadIdx.x;
    const int row0 = blockIdx.x * 128;

    #pragma unroll 4
    for (int i = tid; i < 128 * 32; i += GEMM_TB) {
        int r = i >> 5, c = (i & 31) << 2;
        *(float4*)(sW + r * 128 + c) = *(const float4*)(W + r * DD + c);
    }
    __syncthreads();

    const int tx = tid & 15, ty = tid >> 4;   // 16 col-groups x 64 row-groups
    const int cb = tx * 8;
    const int rb = ty * 2;

    int rowv[2]; float scv[2]; bool vl[2];
    #pragma unroll
    for (int r = 0; r < 2; r++) {
        int rl = row0 + rb + r;
        vl[r] = (rl < m);
        int row = vl[r] ? (rowidx ? rowidx[rl] : rl) : 0;
        rowv[r] = row;
        scv[r] = (scale && vl[r]) ? scale[row] : 1.f;
    }

    unsigned long long acc[2][4] = {};

    #pragma unroll 2
    for (int k0 = 0; k0 < 128; k0 += 4) {
        float av[2][4];
        #pragma unroll
        for (int r = 0; r < 2; r++) {
            float4 v = vl[r] ? *(const float4*)(A + (size_t)rowv[r] * DD + k0)
                             : make_float4(0.f, 0.f, 0.f, 0.f);
            av[r][0] = v.x; av[r][1] = v.y; av[r][2] = v.z; av[r][3] = v.w;
        }
        #pragma unroll
        for (int kk = 0; kk < 4; kk++) {
            ulonglong2 w0 = *(ulonglong2*)(sW + (k0 + kk) * 128 + cb);
            ulonglong2 w1 = *(ulonglong2*)(sW + (k0 + kk) * 128 + cb + 4);
            #pragma unroll
            for (int r = 0; r < 2; r++) {
                unsigned long long aa = pack2(av[r][kk]);
                acc[r][0] = fma2(aa, w0.x, acc[r][0]);
                acc[r][1] = fma2(aa, w0.y, acc[r][1]);
                acc[r][2] = fma2(aa, w1.x, acc[r][2]);
                acc[r][3] = fma2(aa, w1.y, acc[r][3]);
            }
        }
    }

    float4 b0 = *(const float4*)(bias + cb);
    float4 b1 = *(const float4*)(bias + cb + 4);
    #pragma unroll
    for (int r = 0; r < 2; r++) {
        if (vl[r]) {
            float s = scv[r];
            float2 p0 = unpack2(acc[r][0]);
            float2 p1 = unpack2(acc[r][1]);
            float2 p2 = unpack2(acc[r][2]);
            float2 p3 = unpack2(acc[r][3]);
            float4 o0 = make_float4(fmaf(s, p0.x, b0.x), fmaf(s, p0.y, b0.y),
                                    fmaf(s, p1.x, b0.z), fmaf(s, p1.y, b0.w));
            float4 o1 = make_float4(fmaf(s, p2.x, b1.x), fmaf(s, p2.y, b1.y),
                                    fmaf(s, p3.x, b1.z), fmaf(s, p3.y, b1.w));
            float* cp = C + (size_t)rowv[r] * DD + cb;
            *(float4*)(cp)     = o0;
            *(float4*)(cp + 4) = o1;
        }
    }
}

// ----------------------------------------------------------------------------
// Host orchestration (21 launches)
// ----------------------------------------------------------------------------
extern "C" void kernel_launch(void* const* d_in, const int* in_sizes, int n_in,
                              void* d_out, int out_size) {
    const float* x_in = (const float*)d_in[0];
    const int*   ei   = (const int*)d_in[1];
    const float* Wd   = (const float*)d_in[2];
    const float* bd   = (const float*)d_in[3];
    const float* Wu   = (const float*)d_in[4];
    const float* bu   = (const float*)d_in[5];
    const float* Wb   = (const float*)d_in[6];
    const float* bb   = (const float*)d_in[7];
    const float* pvec = (const float*)d_in[8];
    float* out = (float*)d_out;

    float *p_h, *p_t, *p_g, *p_x, *p_d0, *p_d1;
    float *p_ecc0, *p_ecc1, *p_ecc2, *p_ctc0, *p_ctc1, *p_ctr0, *p_ctr1, *p_s;
    int *p_offr, *p_offc, *p_nbrr, *p_nbrc, *p_act0, *p_act1, *p_acnt0, *p_acnt1;
    cudaGetSymbolAddress((void**)&p_h, g_h);
    cudaGetSymbolAddress((void**)&p_t, g_t);
    cudaGetSymbolAddress((void**)&p_g, g_g);
    cudaGetSymbolAddress((void**)&p_x, g_xx);
    cudaGetSymbolAddress((void**)&p_d0, g_d0);
    cudaGetSymbolAddress((void**)&p_d1, g_d1);
    cudaGetSymbolAddress((void**)&p_ecc0, g_ecc0);
    cudaGetSymbolAddress((void**)&p_ecc1, g_ecc1);
    cudaGetSymbolAddress((void**)&p_ecc2, g_ecc2);
    cudaGetSymbolAddress((void**)&p_ctc0, g_ctc0);
    cudaGetSymbolAddress((void**)&p_ctc1, g_ctc1);
    cudaGetSymbolAddress((void**)&p_ctr0, g_ctr0);
    cudaGetSymbolAddress((void**)&p_ctr1, g_ctr1);
    cudaGetSymbolAddress((void**)&p_s, g_s);
    cudaGetSymbolAddress((void**)&p_offr, g_offr);
    cudaGetSymbolAddress((void**)&p_offc, g_offc);
    cudaGetSymbolAddress((void**)&p_nbrr, g_nbrr);
    cudaGetSymbolAddress((void**)&p_nbrc, g_nbrc);
    cudaGetSymbolAddress((void**)&p_act0, g_act0);
    cudaGetSymbolAddress((void**)&p_act1, g_act1);
    cudaGetSymbolAddress((void**)&p_acnt0, g_acnt0);
    cudaGetSymbolAddress((void**)&p_acnt1, g_acnt1);

    cudaFuncSetAttribute(k_gemm, cudaFuncAttributeMaxDynamicSharedMemorySize, GEMM_SMEM);

    const int G_NW   = (NN * 32) / TB;          // 6250 (standalone full gather)
    const int G_NW1  = (K1 * 32) / TB;          // 3125 (standalone K1 gather)
    const int G_GF = (NN + 127) / 128;          // 391
    const int G_G1 = (K1 + 127) / 128;          // 196
    const int G_G2 = (K2 + 127) / 128;          // 98

    // 1: setup (init + hist + scan + fill + prep0)
    k_setup<<<FGRID, TB>>>(pvec, ei);
    // 2: GEMM Wd0
    k_gemm<<<G_GF, GEMM_TB, GEMM_SMEM>>>(x_in, Wd, bd, p_t, nullptr, nullptr, NN);
    // 3: gather ecc0 (t->g)
    k_gather_t<false,false><<<G_NW, TB>>>(p_t, p_g, p_offc, p_nbrc, p_ecc0,
                                          nullptr, nullptr, NN);
    // 4: GEMM Wd1 (profiled slot)
    k_gemm<<<G_GF, GEMM_TB, GEMM_SMEM>>>(p_g, Wd + (size_t)1*DD*DD, bd + 1*DD, p_t,
                                         nullptr, nullptr, NN);
    // 5: pool level 0
    k_pool<false><<<FGRID, TB>>>(p_t, p_d0, p_ecc0, p_h, p_ctc0,
                                 pvec, 0, nullptr, NN, K1, p_act0, p_acnt0);
    // 6: GEMM Wd2 (K1, scale)
    k_gemm<<<G_G1, GEMM_TB, GEMM_SMEM>>>(p_h, Wd + (size_t)2*DD*DD, bd + 2*DD, p_t,
                                         p_s, p_act0, K1);
    // 7: prep1 + gather ecc1 (t->g, K1)
    k_prepgather<<<FGRID, TB>>>(ei, p_ecc1, p_ctc1, p_ctr1, p_t, p_g, p_act0, K1);
    // 8: GEMM Wd3 (K1)
    k_gemm<<<G_G1, GEMM_TB, GEMM_SMEM>>>(p_g, Wd + (size_t)3*DD*DD, bd + 3*DD, p_t,
                                         nullptr, p_act0, K1);
    // 9: pool level 1
    k_pool<true><<<FGRID, TB>>>(p_t, p_d1, p_ecc1, p_h, p_ctc1,
                                pvec + DD, 1, p_act0, K1, K2, p_act1, p_acnt1);
    // 10: GEMM Wb0 (K2, scale)
    k_gemm<<<G_G2, GEMM_TB, GEMM_SMEM>>>(p_h, Wb, bb, p_t, p_s, p_act1, K2);
    // 11: prep2 (ecc only) + gather ecc2 (t->g, K2)
    k_prepgather<<<FGRID, TB>>>(ei, p_ecc2, nullptr, nullptr, p_t, p_g, p_act1, K2);
    // 12: GEMM Wb1 (K2)
    k_gemm<<<G_G2, GEMM_TB, GEMM_SMEM>>>(p_g, Wb + (size_t)1*DD*DD, bb + 1*DD, p_t,
                                         nullptr, p_act1, K2);
    // 13: gather ecc2 (t->x, K1) + gather ctr1 (x->h, K1)
    k_2gather<true,false,true><<<FGRID, TB>>>(p_t, p_x, p_offc, p_nbrc, p_ecc2,
                                              nullptr, p_act0, K1,
                                              p_h, p_offr, p_nbrr, p_ctr1,
                                              p_act0, K1);
    // 14: GEMM Wu0 (K1)
    k_gemm<<<G_G1, GEMM_TB, GEMM_SMEM>>>(p_h, Wu, bu, p_t, nullptr, p_act0, K1);
    // 15: gather ecc1 (t->g, K1) standalone
    k_gather_t<true,false><<<G_NW1, TB>>>(p_t, p_g, p_offc, p_nbrc, p_ecc1,
                                          nullptr, p_act0, K1);
    // 16: GEMM Wu1 (K1)
    k_gemm<<<G_G1, GEMM_TB, GEMM_SMEM>>>(p_g, Wu + (size_t)1*DD*DD, bu + 1*DD, p_t,
                                         nullptr, p_act0, K1);
    // 17: gather ecc1+d1 (t->x full) + gather ctr0 (x->h full)
    k_2gather<true,true,false><<<FGRID, TB>>>(p_t, p_x, p_offc, p_nbrc, p_ecc1,
                                              p_d1, nullptr, NN,
                                              p_h, p_offr, p_nbrr, p_ctr0,
                                              nullptr, NN);
    // 18: GEMM Wu2 (full)
    k_gemm<<<G_GF, GEMM_TB, GEMM_SMEM>>>(p_h, Wu + (size_t)2*DD*DD, bu + 2*DD, p_t,
                                         nullptr, nullptr, NN);
    // 19: gather ecc0 (t->g full) standalone
    k_gather_t<false,false><<<G_NW, TB>>>(p_t, p_g, p_offc, p_nbrc, p_ecc0,
                                          nullptr, nullptr, NN);
    // 20: GEMM Wu3 (full)
    k_gemm<<<G_GF, GEMM_TB, GEMM_SMEM>>>(p_g, Wu + (size_t)3*DD*DD, bu + 3*DD, p_t,
                                         nullptr, nullptr, NN);
    // 21: final gather ecc0+d0 (t->out full) standalone
    k_gather_t<false,true><<<G_NW, TB>>>(p_t, out, p_offc, p_nbrc, p_ecc0,
                                         p_d0, nullptr, NN);
}

// round 16
// speedup vs baseline: 1.3462x; 1.3462x over previous
#include <cuda_runtime.h>
#include <cstdint>

// Problem constants
#define NN 50000
#define DD 128
#define EE 800000
#define ND (NN*DD)
#define TB 256
#define K1 25000
#define K2 12500
#define BAR_GRID 592             // 4 blocks/SM x 148 SMs (co-residency enforced)
#define SCAN_GRID 64

// ----------------------------------------------------------------------------
// Device scratch (allocation-free: __device__ globals)
// ----------------------------------------------------------------------------
__device__ float g_h[ND];
__device__ float g_t[ND];
__device__ float g_g[ND];
__device__ float g_xx[ND];
__device__ float g_d0[ND];
__device__ float g_d1[ND];
__device__ int   g_nbrr[EE];
__device__ int   g_nbrc[EE];
__device__ int   g_ownr[EE];
__device__ int   g_ownc[EE];
__device__ float g_ecc0[EE];
__device__ float g_ecc1[EE];
__device__ float g_ecc2[EE];
__device__ float g_ctc0[EE];
__device__ float g_ctc1[EE];
__device__ float g_ctr0[EE];
__device__ float g_ctr1[EE];
// packed node state: x=nm, y=normed, z=dis, w=aggr
__device__ float4 g_node[NN];
__device__ float g_dsum[NN];     // phase B: deg-sum; phase E onward: inv = nm/aggr
__device__ float g_asum[NN];
__device__ float g_w[NN];
__device__ float g_score[NN];
__device__ float g_s[NN];
__device__ unsigned long long g_key[NN];
__device__ unsigned int g_hist[65536];
__device__ unsigned int g_part2[SCAN_GRID];
__device__ unsigned long long g_prefix;
__device__ int g_k;
__device__ float g_pinv[2];
__device__ int g_cntr[NN];
__device__ int g_cntc[NN];
__device__ int g_offr[NN + 1];
__device__ int g_offc[NN + 1];
__device__ int g_curr[NN];
__device__ int g_curc[NN];
__device__ int g_act0[NN];
__device__ int g_act1[NN];
__device__ int g_acnt0;
__device__ int g_acnt1;
// software grid barrier — self-cleaning across graph replays; NEVER reset.
__device__ int g_barcnt = 0;
__device__ unsigned g_bargen = 0u;

// ----------------------------------------------------------------------------
// f32x2 packed-FMA helpers
// ----------------------------------------------------------------------------
__device__ __forceinline__ unsigned long long fma2(unsigned long long a,
                                                   unsigned long long b,
                                                   unsigned long long c) {
    unsigned long long d;
    asm("fma.rn.f32x2 %0, %1, %2, %3;" : "=l"(d) : "l"(a), "l"(b), "l"(c));
    return d;
}
__device__ __forceinline__ unsigned long long pack2(float x) {
    unsigned long long d;
    asm("mov.b64 %0, {%1, %1};" : "=l"(d) : "f"(x));
    return d;
}
__device__ __forceinline__ float2 unpack2(unsigned long long v) {
    float2 r;
    asm("mov.b64 {%0, %1}, %2;" : "=f"(r.x), "=f"(r.y) : "l"(v));
    return r;
}

// ----------------------------------------------------------------------------
// Software grid barrier (all blocks co-resident)
// ----------------------------------------------------------------------------
__device__ __forceinline__ void gridbar() {
    __syncthreads();
    if (threadIdx.x == 0) {
        unsigned gen = *((volatile unsigned*)&g_bargen);
        __threadfence();
        int ticket = atomicAdd(&g_barcnt, 1);
        if (ticket == (int)gridDim.x - 1) {
            g_barcnt = 0;
            __threadfence();
            atomicAdd(&g_bargen, 1u);
        } else {
            while (*((volatile unsigned*)&g_bargen) == gen) {}
        }
        __threadfence();
    }
    __syncthreads();
}

// ----------------------------------------------------------------------------
// Launch #1: init -> [bar] -> edge histogram   (grid-stride, BAR_GRID blocks)
// ----------------------------------------------------------------------------
__global__ void __launch_bounds__(TB, 4) k_init_hist(const float* __restrict__ pvec,
                                                     const int* __restrict__ ei) {
    int gid = blockIdx.x * blockDim.x + threadIdx.x;
    int gs = gridDim.x * blockDim.x;
    for (int j = gid; j < 65536; j += gs) g_hist[j] = 0u;
    for (int v = gid; v < NN; v += gs) {
        g_node[v] = make_float4(1.f, 0.f, 0.f, 0.f);
        g_w[v] = 1.0f;
        g_cntr[v] = 0; g_cntc[v] = 0;
        g_dsum[v] = 0.f; g_asum[v] = 0.f;
    }
    if (gid == 0) { g_acnt0 = 0; g_acnt1 = 0; }
    if (blockIdx.x == 0 && threadIdx.x < 64) {
        int l = threadIdx.x >> 5, lane = threadIdx.x & 31;
        float4 p = ((const float4*)(pvec + l * DD))[lane];
        float s = p.x*p.x + p.y*p.y + p.z*p.z + p.w*p.w;
        #pragma unroll
        for (int o = 16; o; o >>= 1) s += __shfl_xor_sync(0xffffffffu, s, o);
        if (lane == 0) g_pinv[l] = rsqrtf(s);
    }
    gridbar();
    for (int e = gid; e < EE; e += gs) {
        atomicAdd(&g_cntr[ei[e]], 1);
        atomicAdd(&g_cntc[ei[EE + e]], 1);
    }
}

// ----------------------------------------------------------------------------
// Launch #3: scans (block 0) -> [bar] -> csr fill (+ owner arrays)
// ----------------------------------------------------------------------------
__device__ void scan256(const int* __restrict__ cnt, int* __restrict__ off,
                        int* __restrict__ cur, int* part) {
    const int PER = 196;   // 256*196 = 50176 >= NN
    int t = threadIdx.x;
    int base = t * PER;
    int s = 0;
    for (int i = 0; i < PER; i++) { int idx = base + i; if (idx < NN) s += cnt[idx]; }
    part[t] = s;
    __syncthreads();
    if (t == 0) {
        int acc = 0;
        for (int i = 0; i < 256; i++) { int v = part[i]; part[i] = acc; acc += v; }
        off[NN] = acc;
    }
    __syncthreads();
    int run = part[t];
    for (int i = 0; i < PER; i++) {
        int idx = base + i;
        if (idx < NN) { off[idx] = run; cur[idx] = run; run += cnt[idx]; }
    }
}

__global__ void __launch_bounds__(TB, 4) k_scanfill(const int* __restrict__ ei) {
    __shared__ int part[256];
    int gid = blockIdx.x * blockDim.x + threadIdx.x;
    int gs = gridDim.x * blockDim.x;
    if (blockIdx.x == 0) {
        scan256(g_cntr, g_offr, g_curr, part);
        __syncthreads();
        scan256(g_cntc, g_offc, g_curc, part);
    }
    gridbar();
    for (int e = gid; e < EE; e += gs) {
        int r = ei[e], c = ei[EE + e];
        int pr = atomicAdd(&g_curr[r], 1);
        g_nbrr[pr] = c;
        g_ownr[pr] = r;
        int pc = atomicAdd(&g_curc[c], 1);
        g_nbrc[pc] = r;
        g_ownc[pc] = c;
    }
}

// ----------------------------------------------------------------------------
// Per-level prep: EDGE-PARALLEL, phases with grid barriers (BAR_GRID blocks)
// ----------------------------------------------------------------------------
__global__ void __launch_bounds__(TB, 4) k_prep(const int* __restrict__ ei,
                                                float* __restrict__ ecc,
                                                float* __restrict__ ctc,
                                                float* __restrict__ ctr) {
    int gid = blockIdx.x * blockDim.x + threadIdx.x;
    int gs = gridDim.x * blockDim.x;

    // A: zero reduction buffers
    for (int v = gid; v < NN; v += gs) { g_dsum[v] = 0.f; g_asum[v] = 0.f; }
    gridbar();
    // B: deg-sum (random-address float atomics)
    for (int e = gid; e < EE; e += gs) {
        int r = ei[e], c = ei[EE + e];
        float nmc = __ldg(&g_node[c].x);
        if (nmc != 0.f) atomicAdd(&g_dsum[r], nmc);
    }
    gridbar();
    // C: node derive dis/normed
    for (int v = gid; v < NN; v += gs) {
        float4 n4 = g_node[v];
        float d = n4.x * g_dsum[v];
        if (d > 0.f) { n4.z = rsqrtf(d); n4.y = g_w[v] / d; }
        else         { n4.z = 0.f; n4.y = 0.f; }
        g_node[v] = n4;
    }
    gridbar();
    // D: aggr-sum
    for (int e = gid; e < EE; e += gs) {
        int r = ei[e], c = ei[EE + e];
        float2 rn = *(const float2*)&g_node[r];   // x=nm, y=normed
        float v = rn.y * rn.x;
        if (v != 0.f) atomicAdd(&g_asum[c], v);
    }
    gridbar();
    // E: node derive aggr + inv (inv stored in dsum)
    for (int v = gid; v < NN; v += gs) {
        float4 n4 = g_node[v];
        float aggr = fmaf(n4.x, g_asum[v], 1e-12f);
        n4.w = aggr;
        g_node[v] = n4;
        g_dsum[v] = n4.x / aggr;
    }
    gridbar();
    // F+G: coefficient writes (col-CSR pass; row-CSR pass interleaved)
    for (int i = gid; i < EE; i += gs) {
        {
            int c = g_ownc[i];
            int r = g_nbrc[i];
            float4 nr = g_node[r];
            ecc[i] = nr.z * g_node[c].z;
            if (ctc) ctc[i] = nr.y * nr.x * g_dsum[c];
        }
        if (ctr) {
            int r = g_ownr[i];
            int c = g_nbrr[i];
            float2 rn = *(const float2*)&g_node[r];
            ctr[i] = rn.y * rn.x * g_dsum[c];
        }
    }
}

// ----------------------------------------------------------------------------
// CSR pull-gather (warp per node, float4 per lane); optional node list.
// ----------------------------------------------------------------------------
template<bool SKIP, bool ADDIN, bool SCORE>
__global__ void __launch_bounds__(256) k_gather_t(
    const float* __restrict__ src, float* __restrict__ dst,
    const int* __restrict__ off, const int* __restrict__ nbr,
    const float* __restrict__ cf, const float* __restrict__ addin,
    const float* __restrict__ pv, int lvl,
    const int* __restrict__ list, int nlist) {
    int wid = (blockIdx.x * blockDim.x + threadIdx.x) >> 5;
    if (wid >= nlist) return;
    int v = list ? list[wid] : wid;
    int lane = threadIdx.x & 31;
    int s = off[v], e = off[v + 1];
    float ax = 0.f, ay = 0.f, az = 0.f, aw = 0.f;
    int i = s;
    if (!SKIP) {
        int e8 = s + ((e - s) & ~7);
        for (; i < e8; i += 8) {
            int n[8]; float w[8]; float4 t[8];
            #pragma unroll
            for (int u = 0; u < 8; u++) { n[u] = nbr[i + u]; w[u] = cf[i + u]; }
            #pragma unroll
            for (int u = 0; u < 8; u++)
                t[u] = ((const float4*)src)[(size_t)n[u] * 32 + lane];
            #pragma unroll
            for (int u = 0; u < 8; u++) {
                ax = fmaf(w[u], t[u].x, ax); ay = fmaf(w[u], t[u].y, ay);
                az = fmaf(w[u], t[u].z, az); aw = fmaf(w[u], t[u].w, aw);
            }
        }
    } else {
        for (; i + 4 <= e; i += 4) {
            int   n0 = nbr[i],   n1 = nbr[i+1],   n2 = nbr[i+2],   n3 = nbr[i+3];
            float w0 = cf[i],    w1 = cf[i+1],    w2 = cf[i+2],    w3 = cf[i+3];
            if (w0 != 0.f) {
                float4 t = ((const float4*)src)[(size_t)n0 * 32 + lane];
                ax = fmaf(w0, t.x, ax); ay = fmaf(w0, t.y, ay);
                az = fmaf(w0, t.z, az); aw = fmaf(w0, t.w, aw);
            }
            if (w1 != 0.f) {
                float4 t = ((const float4*)src)[(size_t)n1 * 32 + lane];
                ax = fmaf(w1, t.x, ax); ay = fmaf(w1, t.y, ay);
                az = fmaf(w1, t.z, az); aw = fmaf(w1, t.w, aw);
            }
            if (w2 != 0.f) {
                float4 t = ((const float4*)src)[(size_t)n2 * 32 + lane];
                ax = fmaf(w2, t.x, ax); ay = fmaf(w2, t.y, ay);
                az = fmaf(w2, t.z, az); aw = fmaf(w2, t.w, aw);
            }
            if (w3 != 0.f) {
                float4 t = ((const float4*)src)[(size_t)n3 * 32 + lane];
                ax = fmaf(w3, t.x, ax); ay = fmaf(w3, t.y, ay);
                az = fmaf(w3, t.z, az); aw = fmaf(w3, t.w, aw);
            }
        }
    }
    for (; i < e; i++) {
        int n = nbr[i]; float w = cf[i];
        if (!SKIP || w != 0.f) {
            float4 t = ((const float4*)src)[(size_t)n * 32 + lane];
            ax = fmaf(w, t.x, ax); ay = fmaf(w, t.y, ay);
            az = fmaf(w, t.z, az); aw = fmaf(w, t.w, aw);
        }
    }
    if (ADDIN) {
        float4 a = ((const float4*)addin)[(size_t)v * 32 + lane];
        ax += a.x; ay += a.y; az += a.z; aw += a.w;
    }
    ((float4*)dst)[(size_t)v * 32 + lane] = make_float4(ax, ay, az, aw);
    if (SCORE) {
        float4 p = ((const float4*)pv)[lane];
        float sdot = ax*p.x + ay*p.y + az*p.z + aw*p.w;
        #pragma unroll
        for (int o = 16; o; o >>= 1) sdot += __shfl_xor_sync(0xffffffffu, sdot, o);
        if (lane == 0) g_score[v] = sdot * g_pinv[lvl];
    }
}

// ----------------------------------------------------------------------------
// Dense GEMM v3 + occupancy cap: block = 128 rows x 64 cols, W-half in 32KB
// static smem, A broadcast LDG, 4x8/thread, FFMA2, scale in epilogue.
// __launch_bounds__(256,3) caps regs at 85 -> 3 blocks/SM (occ 50%).
// grid = (ceil(m/128), 2)
// ----------------------------------------------------------------------------
__global__ void __launch_bounds__(256, 3) k_gemm(const float* __restrict__ A,
                                                 const float* __restrict__ W,
                                                 const float* __restrict__ bias,
                                                 float* __restrict__ C,
                                                 const float* __restrict__ scale,
                                                 const int* __restrict__ rowidx,
                                                 int m) {
    __shared__ __align__(16) float sW[128 * 64];
    const int tid = threadIdx.x;
    const int row0 = blockIdx.x * 128;
    const int col0 = blockIdx.y * 64;

    #pragma unroll 4
    for (int i = tid; i < 128 * 16; i += 256) {
        int r = i >> 4, c = (i & 15) << 2;
        *(float4*)(sW + r * 64 + c) = *(const float4*)(W + r * DD + col0 + c);
    }
    __syncthreads();

    const int tx = tid & 7, ty = tid >> 3;
    const int cb = tx * 8;
    const int rb = ty * 4;

    int rowv[4]; float scv[4]; bool vl[4];
    #pragma unroll
    for (int r = 0; r < 4; r++) {
        int rl = row0 + rb + r;
        vl[r] = (rl < m);
        int row = vl[r] ? (rowidx ? rowidx[rl] : rl) : 0;
        rowv[r] = row;
        scv[r] = (scale && vl[r]) ? scale[row] : 1.f;
    }

    unsigned long long acc[4][4] = {};

    #pragma unroll 2
    for (int k0 = 0; k0 < 128; k0 += 4) {
        float av[4][4];
        #pragma unroll
        for (int r = 0; r < 4; r++) {
            float4 v = vl[r] ? *(const float4*)(A + (size_t)rowv[r] * DD + k0)
                             : make_float4(0.f, 0.f, 0.f, 0.f);
            av[r][0] = v.x; av[r][1] = v.y; av[r][2] = v.z; av[r][3] = v.w;
        }
        #pragma unroll
        for (int kk = 0; kk < 4; kk++) {
            ulonglong2 w0 = *(ulonglong2*)(sW + (k0 + kk) * 64 + cb);
            ulonglong2 w1 = *(ulonglong2*)(sW + (k0 + kk) * 64 + cb + 4);
            #pragma unroll
            for (int r = 0; r < 4; r++) {
                unsigned long long aa = pack2(av[r][kk]);
                acc[r][0] = fma2(aa, w0.x, acc[r][0]);
                acc[r][1] = fma2(aa, w0.y, acc[r][1]);
                acc[r][2] = fma2(aa, w1.x, acc[r][2]);
                acc[r][3] = fma2(aa, w1.y, acc[r][3]);
            }
        }
    }

    float4 b0 = *(const float4*)(bias + col0 + cb);
    float4 b1 = *(const float4*)(bias + col0 + cb + 4);
    #pragma unroll
    for (int r = 0; r < 4; r++) {
        if (vl[r]) {
            float s = scv[r];
            float2 p0 = unpack2(acc[r][0]);
            float2 p1 = unpack2(acc[r][1]);
            float2 p2 = unpack2(acc[r][2]);
            float2 p3 = unpack2(acc[r][3]);
            float4 o0 = make_float4(fmaf(s, p0.x, b0.x), fmaf(s, p0.y, b0.y),
                                    fmaf(s, p1.x, b0.z), fmaf(s, p1.y, b0.w));
            float4 o1 = make_float4(fmaf(s, p2.x, b1.x), fmaf(s, p2.y, b1.y),
                                    fmaf(s, p3.x, b1.z), fmaf(s, p3.y, b1.w));
            float* cp = C + (size_t)rowv[r] * DD + col0 + cb;
            *(float4*)(cp)     = o0;
            *(float4*)(cp + 4) = o1;
        }
    }
}

// ----------------------------------------------------------------------------
// TopK: 48-bit keys (score<<16 | (65535-v)), 3 radix passes of 16 bits.
// keys fused with pass-0 count; parallel 64-block scan; apply+compact.
// ----------------------------------------------------------------------------
__global__ void k_keys(int kval) {
    int v = blockIdx.x * blockDim.x + threadIdx.x;
    if (v == 0) { g_prefix = 0ull; g_k = kval; }
    if (v >= NN) return;
    float s = (g_node[v].x > 0.f) ? g_score[v] : __int_as_float(0xff800000);
    unsigned u = __float_as_uint(s);
    u = (u & 0x80000000u) ? ~u : (u | 0x80000000u);
    unsigned long long key = ((unsigned long long)u << 16) |
                             (unsigned long long)(65535u - (unsigned)v);
    g_key[v] = key;
    atomicAdd(&g_hist[(unsigned)(key >> 32)], 1u);   // pass-0 count fused
}

__global__ void k_count(int pass) {   // pass in {1,2}
    int v = blockIdx.x * blockDim.x + threadIdx.x;
    if (v >= NN) return;
    unsigned long long key = g_key[v];
    if ((key >> (48 - 16 * pass)) != g_prefix) return;
    unsigned d = (unsigned)(key >> (32 - 16 * pass)) & 0xFFFFu;
    atomicAdd(&g_hist[d], 1u);
}

// parallel radix-select scan: SCAN_GRID blocks x 256 threads
__global__ void __launch_bounds__(256) k_scanp() {
    __shared__ unsigned red[256];
    __shared__ unsigned sf[256];
    __shared__ int sel_b;
    __shared__ unsigned sel_cum;
    int b = blockIdx.x, t = threadIdx.x;
    int base = b * 1024;

    unsigned s = 0;
    #pragma unroll
    for (int i = 0; i < 4; i++) s += g_hist[base + t + i * 256];
    red[t] = s;
    __syncthreads();
    for (int o = 128; o; o >>= 1) { if (t < o) red[t] += red[t + o]; __syncthreads(); }
    if (t == 0) g_part2[b] = red[0];
    gridbar();

    if (b == 0) {
        if (t == 0) {
            unsigned k = (unsigned)g_k;
            unsigned cum = 0;
            int bb = 0;
            for (bb = SCAN_GRID - 1; bb > 0; bb--) {
                unsigned p = g_part2[bb];
                if (cum + p >= k) break;
                cum += p;
            }
            sel_b = bb;
            sel_cum = cum;
        }
        __syncthreads();
        int bb = sel_b;
        unsigned kk = (unsigned)g_k - sel_cum;
        int sbase = bb * 1024 + t * 4;
        unsigned h0 = g_hist[sbase], h1 = g_hist[sbase + 1];
        unsigned h2 = g_hist[sbase + 2], h3 = g_hist[sbase + 3];
        unsigned gs = h0 + h1 + h2 + h3;
        sf[t] = gs;
        __syncthreads();
        for (int off = 1; off < 256; off <<= 1) {
            unsigned v = sf[t];
            unsigned ad = (t + off < 256) ? sf[t + off] : 0u;
            __syncthreads();
            sf[t] = v + ad;
            __syncthreads();
        }
        unsigned above = (t < 255) ? sf[t + 1] : 0u;
        if (above < kk && sf[t] >= kk) {
            unsigned cum = above;
            int d = sbase;
            if (cum + h3 >= kk)              { d = sbase + 3; }
            else if (cum + h3 + h2 >= kk)    { cum += h3; d = sbase + 2; }
            else if (cum + h3 + h2 + h1 >= kk){ cum += h3 + h2; d = sbase + 1; }
            else                             { cum += h3 + h2 + h1; d = sbase; }
            g_prefix = (g_prefix << 16) | (unsigned long long)(unsigned)d;
            g_k = (int)(kk - cum);
        }
    }
    gridbar();

    #pragma unroll
    for (int i = 0; i < 4; i++) g_hist[base + t + i * 256] = 0u;
}

__global__ void k_applynode(int* __restrict__ act, int* __restrict__ acnt) {
    int v = blockIdx.x * blockDim.x + threadIdx.x;
    if (v >= NN) return;
    bool kept = (g_key[v] >= g_prefix);
    float4 n4 = g_node[v];
    g_w[v] = kept ? n4.w : 0.f;
    g_s[v] = kept ? tanhf(g_score[v]) : 0.f;
    n4.x = kept ? 1.f : 0.f;
    g_node[v] = n4;
    if (kept) {
        int slot = atomicAdd(acnt, 1);
        act[slot] = v;
    }
}

// ----------------------------------------------------------------------------
// Host orchestration
// ----------------------------------------------------------------------------
extern "C" void kernel_launch(void* const* d_in, const int* in_sizes, int n_in,
                              void* d_out, int out_size) {
    const float* x_in = (const float*)d_in[0];
    const int*   ei   = (const int*)d_in[1];
    const float* Wd   = (const float*)d_in[2];
    const float* bd   = (const float*)d_in[3];
    const float* Wu   = (const float*)d_in[4];
    const float* bu   = (const float*)d_in[5];
    const float* Wb   = (const float*)d_in[6];
    const float* bb   = (const float*)d_in[7];
    const float* pvec = (const float*)d_in[8];
    float* out = (float*)d_out;

    float *p_h, *p_t, *p_g, *p_x, *p_d0, *p_d1;
    float *p_ecc0, *p_ecc1, *p_ecc2, *p_ctc0, *p_ctc1, *p_ctr0, *p_ctr1, *p_s;
    int *p_offr, *p_offc, *p_nbrr, *p_nbrc, *p_act0, *p_act1, *p_acnt0, *p_acnt1;
    cudaGetSymbolAddress((void**)&p_h, g_h);
    cudaGetSymbolAddress((void**)&p_t, g_t);
    cudaGetSymbolAddress((void**)&p_g, g_g);
    cudaGetSymbolAddress((void**)&p_x, g_xx);
    cudaGetSymbolAddress((void**)&p_d0, g_d0);
    cudaGetSymbolAddress((void**)&p_d1, g_d1);
    cudaGetSymbolAddress((void**)&p_ecc0, g_ecc0);
    cudaGetSymbolAddress((void**)&p_ecc1, g_ecc1);
    cudaGetSymbolAddress((void**)&p_ecc2, g_ecc2);
    cudaGetSymbolAddress((void**)&p_ctc0, g_ctc0);
    cudaGetSymbolAddress((void**)&p_ctc1, g_ctc1);
    cudaGetSymbolAddress((void**)&p_ctr0, g_ctr0);
    cudaGetSymbolAddress((void**)&p_ctr1, g_ctr1);
    cudaGetSymbolAddress((void**)&p_s, g_s);
    cudaGetSymbolAddress((void**)&p_offr, g_offr);
    cudaGetSymbolAddress((void**)&p_offc, g_offc);
    cudaGetSymbolAddress((void**)&p_nbrr, g_nbrr);
    cudaGetSymbolAddress((void**)&p_nbrc, g_nbrc);
    cudaGetSymbolAddress((void**)&p_act0, g_act0);
    cudaGetSymbolAddress((void**)&p_act1, g_act1);
    cudaGetSymbolAddress((void**)&p_acnt0, g_acnt0);
    cudaGetSymbolAddress((void**)&p_acnt1, g_acnt1);

    const int G_N    = (NN + TB - 1) / TB;      // 196
    const int G_NW   = (NN * 32) / TB;          // 6250  (full gather)
    const int G_NW1  = (K1 * 32) / TB;          // 3125  (act0 gather)
    const int G_NW2  = (K2 * 32 + TB - 1) / TB; // 1563  (act1 gather)
    const dim3 G_GF((NN + 127) / 128, 2);       // 391 x 2
    const dim3 G_G1((K1 + 127) / 128, 2);       // 196 x 2
    const dim3 G_G2((K2 + 127) / 128, 2);       // 98 x 2

    // ---- prefix: init+hist(1), gemm(2), scanfill(3), prep0(4 = profiled) ----
    k_init_hist<<<BAR_GRID, TB>>>(pvec, ei);                                  // #1
    k_gemm<<<G_GF, TB>>>(x_in, Wd, bd, p_t, nullptr, nullptr, NN);            // #2
    k_scanfill<<<BAR_GRID, TB>>>(ei);                                         // #3
    k_prep<<<BAR_GRID, TB>>>(ei, p_ecc0, p_ctc0, p_ctr0);                     // #4 (profiled)

    // ---- down level 0 (dense) ----
    k_gather_t<false,false,false><<<G_NW, TB>>>(p_t, p_g, p_offc, p_nbrc, p_ecc0,
                                                nullptr, nullptr, 0, nullptr, NN);
    k_gemm<<<G_GF, TB>>>(p_g, Wd + (size_t)1*DD*DD, bd + 1*DD, p_t,
                         nullptr, nullptr, NN);
    k_gather_t<false,false,false><<<G_NW, TB>>>(p_t, p_d0, p_offc, p_nbrc, p_ecc0,
                                                nullptr, nullptr, 0, nullptr, NN);
    k_gather_t<false,false,true><<<G_NW, TB>>>(p_d0, p_h, p_offc, p_nbrc, p_ctc0,
                                               nullptr, pvec, 0, nullptr, NN);
    k_keys<<<G_N, TB>>>(K1);
    k_scanp<<<SCAN_GRID, 256>>>();
    for (int p = 1; p < 3; p++) { k_count<<<G_N, TB>>>(p); k_scanp<<<SCAN_GRID, 256>>>(); }
    k_applynode<<<G_N, TB>>>(p_act0, p_acnt0);

    // ---- down level 1 (sparse; act0-compacted where legal) ----
    k_gemm<<<G_G1, TB>>>(p_h, Wd + (size_t)2*DD*DD, bd + 2*DD, p_t,
                         p_s, p_act0, K1);
    k_prep<<<BAR_GRID, TB>>>(ei, p_ecc1, p_ctc1, p_ctr1);
    k_gather_t<true,false,false><<<G_NW1, TB>>>(p_t, p_g, p_offc, p_nbrc, p_ecc1,
                                                nullptr, nullptr, 0, p_act0, K1);
    k_gemm<<<G_G1, TB>>>(p_g, Wd + (size_t)3*DD*DD, bd + 3*DD, p_t,
                         nullptr, p_act0, K1);
    // d1 must be dense-valid (read as dense addin later) -> full gather
    k_gather_t<true,false,false><<<G_NW, TB>>>(p_t, p_d1, p_offc, p_nbrc, p_ecc1,
                                               nullptr, nullptr, 0, nullptr, NN);
    k_gather_t<true,false,true><<<G_NW1, TB>>>(p_d1, p_h, p_offc, p_nbrc, p_ctc1,
                                               nullptr, pvec + DD, 1, p_act0, K1);
    k_keys<<<G_N, TB>>>(K2);
    k_scanp<<<SCAN_GRID, 256>>>();
    for (int p = 1; p < 3; p++) { k_count<<<G_N, TB>>>(p); k_scanp<<<SCAN_GRID, 256>>>(); }
    k_applynode<<<G_N, TB>>>(p_act1, p_acnt1);

    // ---- bottom ----
    k_gemm<<<G_G2, TB>>>(p_h, Wb, bb, p_t, p_s, p_act1, K2);
    k_prep<<<BAR_GRID, TB>>>(ei, p_ecc2, nullptr, nullptr);
    k_gather_t<true,false,false><<<G_NW2, TB>>>(p_t, p_g, p_offc, p_nbrc, p_ecc2,
                                                nullptr, nullptr, 0, p_act1, K2);
    k_gemm<<<G_G2, TB>>>(p_g, Wb + (size_t)1*DD*DD, bb + 1*DD, p_t,
                         nullptr, p_act1, K2);
    // x must be valid for all act0 nodes (read by ctr1 gather) -> act0 list
    k_gather_t<true,false,false><<<G_NW1, TB>>>(p_t, p_x, p_offc, p_nbrc, p_ecc2,
                                                nullptr, nullptr, 0, p_act0, K1);

    // ---- up level 0 (act0 domain) ----
    k_gather_t<true,false,false><<<G_NW1, TB>>>(p_x, p_h, p_offr, p_nbrr, p_ctr1,
                                                nullptr, nullptr, 0, p_act0, K1);
    k_gemm<<<G_G1, TB>>>(p_h, Wu, bu, p_t, nullptr, p_act0, K1);
    k_gather_t<true,false,false><<<G_NW1, TB>>>(p_t, p_g, p_offc, p_nbrc, p_ecc1,
                                                nullptr, nullptr, 0, p_act0, K1);
    k_gemm<<<G_G1, TB>>>(p_g, Wu + (size_t)1*DD*DD, bu + 1*DD, p_t,
                         nullptr, p_act0, K1);
    // x = gather + d1 must be dense-valid (read by dense ctr0 gather) -> full
    k_gather_t<true,true,false><<<G_NW, TB>>>(p_t, p_x, p_offc, p_nbrc, p_ecc1,
                                              p_d1, nullptr, 0, nullptr, NN);

    // ---- up level 1 (dense, full graph) ----
    k_gather_t<false,false,false><<<G_NW, TB>>>(p_x, p_h, p_offr, p_nbrr, p_ctr0,
                                                nullptr, nullptr, 0, nullptr, NN);
    k_gemm<<<G_GF, TB>>>(p_h, Wu + (size_t)2*DD*DD, bu + 2*DD, p_t,
                         nullptr, nullptr, NN);
    k_gather_t<false,false,false><<<G_NW, TB>>>(p_t, p_g, p_offc, p_nbrc, p_ecc0,
                                                nullptr, nullptr, 0, nullptr, NN);
    k_gemm<<<G_GF, TB>>>(p_g, Wu + (size_t)3*DD*DD, bu + 3*DD, p_t,
                         nullptr, nullptr, NN);
    k_gather_t<false,true,false><<<G_NW, TB>>>(p_t, out, p_offc, p_nbrc, p_ecc0,
                                               p_d0, nullptr, 0, nullptr, NN);
}

// round 17
// speedup vs baseline: 1.3646x; 1.0136x over previous
#include <cuda_runtime.h>
#include <cstdint>

// Problem constants
#define NN 50000
#define DD 128
#define EE 800000
#define ND (NN*DD)
#define TB 256
#define K1 25000
#define K2 12500
#define BAR_GRID 888             // 6 blocks/SM x 148 SMs (co-residency enforced)
#define SCAN_GRID 64

// ----------------------------------------------------------------------------
// Device scratch (allocation-free: __device__ globals)
// ----------------------------------------------------------------------------
__device__ float g_h[ND];
__device__ float g_t[ND];
__device__ float g_g[ND];
__device__ float g_xx[ND];
__device__ float g_d0[ND];
__device__ float g_d1[ND];
__device__ int   g_nbrr[EE];
__device__ int   g_nbrc[EE];
__device__ int   g_ownr[EE];
__device__ int   g_ownc[EE];
__device__ float g_ecc0[EE];
__device__ float g_ecc1[EE];
__device__ float g_ecc2[EE];
__device__ float g_ctc0[EE];
__device__ float g_ctc1[EE];
__device__ float g_ctr0[EE];
__device__ float g_ctr1[EE];
// packed node state: x=nm, y=normed, z=dis, w=aggr
__device__ float4 g_node[NN];
__device__ float g_dsum[NN];     // deg-sum; after phase E: inv = nm/aggr
__device__ float g_asum[NN];
__device__ float g_w[NN];
__device__ float g_score[NN];
__device__ float g_s[NN];
__device__ unsigned long long g_key[NN];
__device__ unsigned int g_hist[65536];
__device__ unsigned int g_part2[SCAN_GRID];
__device__ unsigned long long g_prefix;
__device__ int g_k;
__device__ float g_pinv[2];
__device__ int g_cntr[NN];
__device__ int g_cntc[NN];
__device__ int g_offr[NN + 1];
__device__ int g_offc[NN + 1];
__device__ int g_curr[NN];
__device__ int g_curc[NN];
__device__ int g_act0[NN];
__device__ int g_act1[NN];
__device__ int g_acnt0;
__device__ int g_acnt1;
// software grid barrier — self-cleaning across graph replays; NEVER reset.
__device__ int g_barcnt = 0;
__device__ unsigned g_bargen = 0u;

// ----------------------------------------------------------------------------
// f32x2 packed-FMA helpers
// ----------------------------------------------------------------------------
__device__ __forceinline__ unsigned long long fma2(unsigned long long a,
                                                   unsigned long long b,
                                                   unsigned long long c) {
    unsigned long long d;
    asm("fma.rn.f32x2 %0, %1, %2, %3;" : "=l"(d) : "l"(a), "l"(b), "l"(c));
    return d;
}
__device__ __forceinline__ unsigned long long pack2(float x) {
    unsigned long long d;
    asm("mov.b64 %0, {%1, %1};" : "=l"(d) : "f"(x));
    return d;
}
__device__ __forceinline__ float2 unpack2(unsigned long long v) {
    float2 r;
    asm("mov.b64 {%0, %1}, %2;" : "=f"(r.x), "=f"(r.y) : "l"(v));
    return r;
}

// ----------------------------------------------------------------------------
// Software grid barrier (all blocks co-resident)
// ----------------------------------------------------------------------------
__device__ __forceinline__ void gridbar() {
    __syncthreads();
    if (threadIdx.x == 0) {
        unsigned gen = *((volatile unsigned*)&g_bargen);
        __threadfence();
        int ticket = atomicAdd(&g_barcnt, 1);
        if (ticket == (int)gridDim.x - 1) {
            g_barcnt = 0;
            __threadfence();
            atomicAdd(&g_bargen, 1u);
        } else {
            while (*((volatile unsigned*)&g_bargen) == gen) {}
        }
        __threadfence();
    }
    __syncthreads();
}

// ----------------------------------------------------------------------------
// Launch #1: init -> [bar] -> edge histogram   (grid-stride, BAR_GRID blocks)
// ----------------------------------------------------------------------------
__global__ void __launch_bounds__(TB, 6) k_init_hist(const float* __restrict__ pvec,
                                                     const int* __restrict__ ei) {
    int gid = blockIdx.x * blockDim.x + threadIdx.x;
    int gs = gridDim.x * blockDim.x;
    for (int j = gid; j < 65536; j += gs) g_hist[j] = 0u;
    for (int v = gid; v < NN; v += gs) {
        g_node[v] = make_float4(1.f, 0.f, 0.f, 0.f);
        g_w[v] = 1.0f;
        g_cntr[v] = 0; g_cntc[v] = 0;
        g_dsum[v] = 0.f; g_asum[v] = 0.f;
    }
    if (gid == 0) { g_acnt0 = 0; g_acnt1 = 0; }
    if (blockIdx.x == 0 && threadIdx.x < 64) {
        int l = threadIdx.x >> 5, lane = threadIdx.x & 31;
        float4 p = ((const float4*)(pvec + l * DD))[lane];
        float s = p.x*p.x + p.y*p.y + p.z*p.z + p.w*p.w;
        #pragma unroll
        for (int o = 16; o; o >>= 1) s += __shfl_xor_sync(0xffffffffu, s, o);
        if (lane == 0) g_pinv[l] = rsqrtf(s);
    }
    gridbar();
    // batched ×4 edge histogram
    for (int e = gid; e < EE; e += 4 * gs) {
        int rr[4], cc[4]; bool ok[4];
        #pragma unroll
        for (int u = 0; u < 4; u++) {
            int ee = e + u * gs;
            ok[u] = (ee < EE);
            rr[u] = ok[u] ? ei[ee] : 0;
            cc[u] = ok[u] ? ei[EE + ee] : 0;
        }
        #pragma unroll
        for (int u = 0; u < 4; u++) {
            if (ok[u]) {
                atomicAdd(&g_cntr[rr[u]], 1);
                atomicAdd(&g_cntc[cc[u]], 1);
            }
        }
    }
}

// ----------------------------------------------------------------------------
// Launch #3: scans (block 0) -> [bar] -> csr fill (+ owner arrays)
// ----------------------------------------------------------------------------
__device__ void scan256(const int* __restrict__ cnt, int* __restrict__ off,
                        int* __restrict__ cur, int* part) {
    const int PER = 196;   // 256*196 = 50176 >= NN
    int t = threadIdx.x;
    int base = t * PER;
    int s = 0;
    for (int i = 0; i < PER; i++) { int idx = base + i; if (idx < NN) s += cnt[idx]; }
    part[t] = s;
    __syncthreads();
    if (t == 0) {
        int acc = 0;
        for (int i = 0; i < 256; i++) { int v = part[i]; part[i] = acc; acc += v; }
        off[NN] = acc;
    }
    __syncthreads();
    int run = part[t];
    for (int i = 0; i < PER; i++) {
        int idx = base + i;
        if (idx < NN) { off[idx] = run; cur[idx] = run; run += cnt[idx]; }
    }
}

__global__ void __launch_bounds__(TB, 6) k_scanfill(const int* __restrict__ ei) {
    __shared__ int part[256];
    int gid = blockIdx.x * blockDim.x + threadIdx.x;
    int gs = gridDim.x * blockDim.x;
    if (blockIdx.x == 0) {
        scan256(g_cntr, g_offr, g_curr, part);
        __syncthreads();
        scan256(g_cntc, g_offc, g_curc, part);
    }
    gridbar();
    for (int e = gid; e < EE; e += gs) {
        int r = ei[e], c = ei[EE + e];
        int pr = atomicAdd(&g_curr[r], 1);
        g_nbrr[pr] = c;
        g_ownr[pr] = r;
        int pc = atomicAdd(&g_curc[c], 1);
        g_nbrc[pc] = r;
        g_ownc[pc] = c;
    }
}

// ----------------------------------------------------------------------------
// Per-level prep: EDGE-PARALLEL, batched ×4, no zero-phase (pre-zeroed by
// init/applynode). BAR_GRID=888 blocks, 6/SM.
// ----------------------------------------------------------------------------
__global__ void __launch_bounds__(TB, 6) k_prep(const int* __restrict__ ei,
                                                float* __restrict__ ecc,
                                                float* __restrict__ ctc,
                                                float* __restrict__ ctr) {
    int gid = blockIdx.x * blockDim.x + threadIdx.x;
    int gs = gridDim.x * blockDim.x;

    // B: deg-sum (batched random-address float atomics)
    for (int e = gid; e < EE; e += 4 * gs) {
        int rr[4]; float nv[4]; bool ok[4];
        #pragma unroll
        for (int u = 0; u < 4; u++) {
            int ee = e + u * gs;
            ok[u] = (ee < EE);
            rr[u] = ok[u] ? ei[ee] : 0;
            int c = ok[u] ? ei[EE + ee] : 0;
            nv[u] = ok[u] ? __ldg(&g_node[c].x) : 0.f;
        }
        #pragma unroll
        for (int u = 0; u < 4; u++)
            if (ok[u] && nv[u] != 0.f) atomicAdd(&g_dsum[rr[u]], nv[u]);
    }
    gridbar();
    // C: node derive dis/normed
    for (int v = gid; v < NN; v += gs) {
        float4 n4 = g_node[v];
        float d = n4.x * g_dsum[v];
        if (d > 0.f) { n4.z = rsqrtf(d); n4.y = g_w[v] / d; }
        else         { n4.z = 0.f; n4.y = 0.f; }
        g_node[v] = n4;
    }
    gridbar();
    // D: aggr-sum (batched)
    for (int e = gid; e < EE; e += 4 * gs) {
        int cc[4]; float vv[4]; bool ok[4];
        #pragma unroll
        for (int u = 0; u < 4; u++) {
            int ee = e + u * gs;
            ok[u] = (ee < EE);
            int r = ok[u] ? ei[ee] : 0;
            cc[u] = ok[u] ? ei[EE + ee] : 0;
            float2 rn = ok[u] ? *(const float2*)&g_node[r] : make_float2(0.f, 0.f);
            vv[u] = rn.y * rn.x;
        }
        #pragma unroll
        for (int u = 0; u < 4; u++)
            if (ok[u] && vv[u] != 0.f) atomicAdd(&g_asum[cc[u]], vv[u]);
    }
    gridbar();
    // E: node derive aggr + inv (inv stored in dsum)
    for (int v = gid; v < NN; v += gs) {
        float4 n4 = g_node[v];
        float aggr = fmaf(n4.x, g_asum[v], 1e-12f);
        n4.w = aggr;
        g_node[v] = n4;
        g_dsum[v] = n4.x / aggr;
    }
    gridbar();
    // F+G: coefficient writes (col pass; row pass interleaved)
    for (int i = gid; i < EE; i += gs) {
        {
            int c = g_ownc[i];
            int r = g_nbrc[i];
            float4 nr = g_node[r];
            ecc[i] = nr.z * g_node[c].z;
            if (ctc) ctc[i] = nr.y * nr.x * g_dsum[c];
        }
        if (ctr) {
            int r = g_ownr[i];
            int c = g_nbrr[i];
            float2 rn = *(const float2*)&g_node[r];
            ctr[i] = rn.y * rn.x * g_dsum[c];
        }
    }
}

// ----------------------------------------------------------------------------
// CSR pull-gather (warp per node, float4 per lane); optional node list.
// ----------------------------------------------------------------------------
template<bool SKIP, bool ADDIN, bool SCORE>
__global__ void __launch_bounds__(256) k_gather_t(
    const float* __restrict__ src, float* __restrict__ dst,
    const int* __restrict__ off, const int* __restrict__ nbr,
    const float* __restrict__ cf, const float* __restrict__ addin,
    const float* __restrict__ pv, int lvl,
    const int* __restrict__ list, int nlist) {
    int wid = (blockIdx.x * blockDim.x + threadIdx.x) >> 5;
    if (wid >= nlist) return;
    int v = list ? list[wid] : wid;
    int lane = threadIdx.x & 31;
    int s = off[v], e = off[v + 1];
    float ax = 0.f, ay = 0.f, az = 0.f, aw = 0.f;
    int i = s;
    if (!SKIP) {
        int e8 = s + ((e - s) & ~7);
        for (; i < e8; i += 8) {
            int n[8]; float w[8]; float4 t[8];
            #pragma unroll
            for (int u = 0; u < 8; u++) { n[u] = nbr[i + u]; w[u] = cf[i + u]; }
            #pragma unroll
            for (int u = 0; u < 8; u++)
                t[u] = ((const float4*)src)[(size_t)n[u] * 32 + lane];
            #pragma unroll
            for (int u = 0; u < 8; u++) {
                ax = fmaf(w[u], t[u].x, ax); ay = fmaf(w[u], t[u].y, ay);
                az = fmaf(w[u], t[u].z, az); aw = fmaf(w[u], t[u].w, aw);
            }
        }
    } else {
        for (; i + 4 <= e; i += 4) {
            int   n0 = nbr[i],   n1 = nbr[i+1],   n2 = nbr[i+2],   n3 = nbr[i+3];
            float w0 = cf[i],    w1 = cf[i+1],    w2 = cf[i+2],    w3 = cf[i+3];
            if (w0 != 0.f) {
                float4 t = ((const float4*)src)[(size_t)n0 * 32 + lane];
                ax = fmaf(w0, t.x, ax); ay = fmaf(w0, t.y, ay);
                az = fmaf(w0, t.z, az); aw = fmaf(w0, t.w, aw);
            }
            if (w1 != 0.f) {
                float4 t = ((const float4*)src)[(size_t)n1 * 32 + lane];
                ax = fmaf(w1, t.x, ax); ay = fmaf(w1, t.y, ay);
                az = fmaf(w1, t.z, az); aw = fmaf(w1, t.w, aw);
            }
            if (w2 != 0.f) {
                float4 t = ((const float4*)src)[(size_t)n2 * 32 + lane];
                ax = fmaf(w2, t.x, ax); ay = fmaf(w2, t.y, ay);
                az = fmaf(w2, t.z, az); aw = fmaf(w2, t.w, aw);
            }
            if (w3 != 0.f) {
                float4 t = ((const float4*)src)[(size_t)n3 * 32 + lane];
                ax = fmaf(w3, t.x, ax); ay = fmaf(w3, t.y, ay);
                az = fmaf(w3, t.z, az); aw = fmaf(w3, t.w, aw);
            }
        }
    }
    for (; i < e; i++) {
        int n = nbr[i]; float w = cf[i];
        if (!SKIP || w != 0.f) {
            float4 t = ((const float4*)src)[(size_t)n * 32 + lane];
            ax = fmaf(w, t.x, ax); ay = fmaf(w, t.y, ay);
            az = fmaf(w, t.z, az); aw = fmaf(w, t.w, aw);
        }
    }
    if (ADDIN) {
        float4 a = ((const float4*)addin)[(size_t)v * 32 + lane];
        ax += a.x; ay += a.y; az += a.z; aw += a.w;
    }
    ((float4*)dst)[(size_t)v * 32 + lane] = make_float4(ax, ay, az, aw);
    if (SCORE) {
        float4 p = ((const float4*)pv)[lane];
        float sdot = ax*p.x + ay*p.y + az*p.z + aw*p.w;
        #pragma unroll
        for (int o = 16; o; o >>= 1) sdot += __shfl_xor_sync(0xffffffffu, sdot, o);
        if (lane == 0) g_score[v] = sdot * g_pinv[lvl];
    }
}

// ----------------------------------------------------------------------------
// Dense GEMM v3 + occupancy cap (R16 WIN — do not touch):
// 128 rows x 64 cols, W-half in 32KB static smem, A broadcast LDG,
// 4x8/thread, FFMA2, scale in epilogue, 3 blocks/SM. grid=(ceil(m/128),2)
// ----------------------------------------------------------------------------
__global__ void __launch_bounds__(256, 3) k_gemm(const float* __restrict__ A,
                                                 const float* __restrict__ W,
                                                 const float* __restrict__ bias,
                                                 float* __restrict__ C,
                                                 const float* __restrict__ scale,
                                                 const int* __restrict__ rowidx,
                                                 int m) {
    __shared__ __align__(16) float sW[128 * 64];
    const int tid = threadIdx.x;
    const int row0 = blockIdx.x * 128;
    const int col0 = blockIdx.y * 64;

    #pragma unroll 4
    for (int i = tid; i < 128 * 16; i += 256) {
        int r = i >> 4, c = (i & 15) << 2;
        *(float4*)(sW + r * 64 + c) = *(const float4*)(W + r * DD + col0 + c);
    }
    __syncthreads();

    const int tx = tid & 7, ty = tid >> 3;
    const int cb = tx * 8;
    const int rb = ty * 4;

    int rowv[4]; float scv[4]; bool vl[4];
    #pragma unroll
    for (int r = 0; r < 4; r++) {
        int rl = row0 + rb + r;
        vl[r] = (rl < m);
        int row = vl[r] ? (rowidx ? rowidx[rl] : rl) : 0;
        rowv[r] = row;
        scv[r] = (scale && vl[r]) ? scale[row] : 1.f;
    }

    unsigned long long acc[4][4] = {};

    #pragma unroll 2
    for (int k0 = 0; k0 < 128; k0 += 4) {
        float av[4][4];
        #pragma unroll
        for (int r = 0; r < 4; r++) {
            float4 v = vl[r] ? *(const float4*)(A + (size_t)rowv[r] * DD + k0)
                             : make_float4(0.f, 0.f, 0.f, 0.f);
            av[r][0] = v.x; av[r][1] = v.y; av[r][2] = v.z; av[r][3] = v.w;
        }
        #pragma unroll
        for (int kk = 0; kk < 4; kk++) {
            ulonglong2 w0 = *(ulonglong2*)(sW + (k0 + kk) * 64 + cb);
            ulonglong2 w1 = *(ulonglong2*)(sW + (k0 + kk) * 64 + cb + 4);
            #pragma unroll
            for (int r = 0; r < 4; r++) {
                unsigned long long aa = pack2(av[r][kk]);
                acc[r][0] = fma2(aa, w0.x, acc[r][0]);
                acc[r][1] = fma2(aa, w0.y, acc[r][1]);
                acc[r][2] = fma2(aa, w1.x, acc[r][2]);
                acc[r][3] = fma2(aa, w1.y, acc[r][3]);
            }
        }
    }

    float4 b0 = *(const float4*)(bias + col0 + cb);
    float4 b1 = *(const float4*)(bias + col0 + cb + 4);
    #pragma unroll
    for (int r = 0; r < 4; r++) {
        if (vl[r]) {
            float s = scv[r];
            float2 p0 = unpack2(acc[r][0]);
            float2 p1 = unpack2(acc[r][1]);
            float2 p2 = unpack2(acc[r][2]);
            float2 p3 = unpack2(acc[r][3]);
            float4 o0 = make_float4(fmaf(s, p0.x, b0.x), fmaf(s, p0.y, b0.y),
                                    fmaf(s, p1.x, b0.z), fmaf(s, p1.y, b0.w));
            float4 o1 = make_float4(fmaf(s, p2.x, b1.x), fmaf(s, p2.y, b1.y),
                                    fmaf(s, p3.x, b1.z), fmaf(s, p3.y, b1.w));
            float* cp = C + (size_t)rowv[r] * DD + col0 + cb;
            *(float4*)(cp)     = o0;
            *(float4*)(cp + 4) = o1;
        }
    }
}

// ----------------------------------------------------------------------------
// TopK: 48-bit keys, 3 radix passes; keys fused with pass-0 count;
// parallel 64-block scan; apply+compact (+ zero dsum/asum for next prep).
// ----------------------------------------------------------------------------
__global__ void k_keys(int kval) {
    int v = blockIdx.x * blockDim.x + threadIdx.x;
    if (v == 0) { g_prefix = 0ull; g_k = kval; }
    if (v >= NN) return;
    float s = (g_node[v].x > 0.f) ? g_score[v] : __int_as_float(0xff800000);
    unsigned u = __float_as_uint(s);
    u = (u & 0x80000000u) ? ~u : (u | 0x80000000u);
    unsigned long long key = ((unsigned long long)u << 16) |
                             (unsigned long long)(65535u - (unsigned)v);
    g_key[v] = key;
    atomicAdd(&g_hist[(unsigned)(key >> 32)], 1u);   // pass-0 count fused
}

__global__ void k_count(int pass) {   // pass in {1,2}
    int v = blockIdx.x * blockDim.x + threadIdx.x;
    if (v >= NN) return;
    unsigned long long key = g_key[v];
    if ((key >> (48 - 16 * pass)) != g_prefix) return;
    unsigned d = (unsigned)(key >> (32 - 16 * pass)) & 0xFFFFu;
    atomicAdd(&g_hist[d], 1u);
}

// parallel radix-select scan: SCAN_GRID blocks x 256 threads
__global__ void __launch_bounds__(256) k_scanp() {
    __shared__ unsigned red[256];
    __shared__ unsigned sf[256];
    __shared__ int sel_b;
    __shared__ unsigned sel_cum;
    int b = blockIdx.x, t = threadIdx.x;
    int base = b * 1024;

    unsigned s = 0;
    #pragma unroll
    for (int i = 0; i < 4; i++) s += g_hist[base + t + i * 256];
    red[t] = s;
    __syncthreads();
    for (int o = 128; o; o >>= 1) { if (t < o) red[t] += red[t + o]; __syncthreads(); }
    if (t == 0) g_part2[b] = red[0];
    gridbar();

    if (b == 0) {
        if (t == 0) {
            unsigned k = (unsigned)g_k;
            unsigned cum = 0;
            int bb = 0;
            for (bb = SCAN_GRID - 1; bb > 0; bb--) {
                unsigned p = g_part2[bb];
                if (cum + p >= k) break;
                cum += p;
            }
            sel_b = bb;
            sel_cum = cum;
        }
        __syncthreads();
        int bb = sel_b;
        unsigned kk = (unsigned)g_k - sel_cum;
        int sbase = bb * 1024 + t * 4;
        unsigned h0 = g_hist[sbase], h1 = g_hist[sbase + 1];
        unsigned h2 = g_hist[sbase + 2], h3 = g_hist[sbase + 3];
        unsigned gs = h0 + h1 + h2 + h3;
        sf[t] = gs;
        __syncthreads();
        for (int off = 1; off < 256; off <<= 1) {
            unsigned v = sf[t];
            unsigned ad = (t + off < 256) ? sf[t + off] : 0u;
            __syncthreads();
            sf[t] = v + ad;
            __syncthreads();
        }
        unsigned above = (t < 255) ? sf[t + 1] : 0u;
        if (above < kk && sf[t] >= kk) {
            unsigned cum = above;
            int d = sbase;
            if (cum + h3 >= kk)              { d = sbase + 3; }
            else if (cum + h3 + h2 >= kk)    { cum += h3; d = sbase + 2; }
            else if (cum + h3 + h2 + h1 >= kk){ cum += h3 + h2; d = sbase + 1; }
            else                             { cum += h3 + h2 + h1; d = sbase; }
            g_prefix = (g_prefix << 16) | (unsigned long long)(unsigned)d;
            g_k = (int)(kk - cum);
        }
    }
    gridbar();

    #pragma unroll
    for (int i = 0; i < 4; i++) g_hist[base + t + i * 256] = 0u;
}

__global__ void k_applynode(int* __restrict__ act, int* __restrict__ acnt) {
    int v = blockIdx.x * blockDim.x + threadIdx.x;
    if (v >= NN) return;
    bool kept = (g_key[v] >= g_prefix);
    float4 n4 = g_node[v];
    g_w[v] = kept ? n4.w : 0.f;
    g_s[v] = kept ? tanhf(g_score[v]) : 0.f;
    n4.x = kept ? 1.f : 0.f;
    g_node[v] = n4;
    if (kept) {
        int slot = atomicAdd(acnt, 1);
        act[slot] = v;
    }
    g_dsum[v] = 0.f;   // pre-zero reduction buffers for the next prep
    g_asum[v] = 0.f;
}

// ----------------------------------------------------------------------------
// Host orchestration
// ----------------------------------------------------------------------------
extern "C" void kernel_launch(void* const* d_in, const int* in_sizes, int n_in,
                              void* d_out, int out_size) {
    const float* x_in = (const float*)d_in[0];
    const int*   ei   = (const int*)d_in[1];
    const float* Wd   = (const float*)d_in[2];
    const float* bd   = (const float*)d_in[3];
    const float* Wu   = (const float*)d_in[4];
    const float* bu   = (const float*)d_in[5];
    const float* Wb   = (const float*)d_in[6];
    const float* bb   = (const float*)d_in[7];
    const float* pvec = (const float*)d_in[8];
    float* out = (float*)d_out;

    float *p_h, *p_t, *p_g, *p_x, *p_d0, *p_d1;
    float *p_ecc0, *p_ecc1, *p_ecc2, *p_ctc0, *p_ctc1, *p_ctr0, *p_ctr1, *p_s;
    int *p_offr, *p_offc, *p_nbrr, *p_nbrc, *p_act0, *p_act1, *p_acnt0, *p_acnt1;
    cudaGetSymbolAddress((void**)&p_h, g_h);
    cudaGetSymbolAddress((void**)&p_t, g_t);
    cudaGetSymbolAddress((void**)&p_g, g_g);
    cudaGetSymbolAddress((void**)&p_x, g_xx);
    cudaGetSymbolAddress((void**)&p_d0, g_d0);
    cudaGetSymbolAddress((void**)&p_d1, g_d1);
    cudaGetSymbolAddress((void**)&p_ecc0, g_ecc0);
    cudaGetSymbolAddress((void**)&p_ecc1, g_ecc1);
    cudaGetSymbolAddress((void**)&p_ecc2, g_ecc2);
    cudaGetSymbolAddress((void**)&p_ctc0, g_ctc0);
    cudaGetSymbolAddress((void**)&p_ctc1, g_ctc1);
    cudaGetSymbolAddress((void**)&p_ctr0, g_ctr0);
    cudaGetSymbolAddress((void**)&p_ctr1, g_ctr1);
    cudaGetSymbolAddress((void**)&p_s, g_s);
    cudaGetSymbolAddress((void**)&p_offr, g_offr);
    cudaGetSymbolAddress((void**)&p_offc, g_offc);
    cudaGetSymbolAddress((void**)&p_nbrr, g_nbrr);
    cudaGetSymbolAddress((void**)&p_nbrc, g_nbrc);
    cudaGetSymbolAddress((void**)&p_act0, g_act0);
    cudaGetSymbolAddress((void**)&p_act1, g_act1);
    cudaGetSymbolAddress((void**)&p_acnt0, g_acnt0);
    cudaGetSymbolAddress((void**)&p_acnt1, g_acnt1);

    const int G_N    = (NN + TB - 1) / TB;      // 196
    const int G_NW   = (NN * 32) / TB;          // 6250  (full gather)
    const int G_NW1  = (K1 * 32) / TB;          // 3125  (act0 gather)
    const int G_NW2  = (K2 * 32 + TB - 1) / TB; // 1563  (act1 gather)
    const dim3 G_GF((NN + 127) / 128, 2);       // 391 x 2
    const dim3 G_G1((K1 + 127) / 128, 2);       // 196 x 2
    const dim3 G_G2((K2 + 127) / 128, 2);       // 98 x 2

    // ---- prefix: init+hist(1), gemm(2), scanfill(3), prep0(4 = profiled) ----
    k_init_hist<<<BAR_GRID, TB>>>(pvec, ei);                                  // #1
    k_gemm<<<G_GF, TB>>>(x_in, Wd, bd, p_t, nullptr, nullptr, NN);            // #2
    k_scanfill<<<BAR_GRID, TB>>>(ei);                                         // #3
    k_prep<<<BAR_GRID, TB>>>(ei, p_ecc0, p_ctc0, p_ctr0);                     // #4 (profiled)

    // ---- down level 0 (dense) ----
    k_gather_t<false,false,false><<<G_NW, TB>>>(p_t, p_g, p_offc, p_nbrc, p_ecc0,
                                                nullptr, nullptr, 0, nullptr, NN);
    k_gemm<<<G_GF, TB>>>(p_g, Wd + (size_t)1*DD*DD, bd + 1*DD, p_t,
                         nullptr, nullptr, NN);
    k_gather_t<false,false,false><<<G_NW, TB>>>(p_t, p_d0, p_offc, p_nbrc, p_ecc0,
                                                nullptr, nullptr, 0, nullptr, NN);
    k_gather_t<false,false,true><<<G_NW, TB>>>(p_d0, p_h, p_offc, p_nbrc, p_ctc0,
                                               nullptr, pvec, 0, nullptr, NN);
    k_keys<<<G_N, TB>>>(K1);
    k_scanp<<<SCAN_GRID, 256>>>();
    for (int p = 1; p < 3; p++) { k_count<<<G_N, TB>>>(p); k_scanp<<<SCAN_GRID, 256>>>(); }
    k_applynode<<<G_N, TB>>>(p_act0, p_acnt0);

    // ---- down level 1 (sparse; act0-compacted where legal) ----
    k_gemm<<<G_G1, TB>>>(p_h, Wd + (size_t)2*DD*DD, bd + 2*DD, p_t,
                         p_s, p_act0, K1);
    k_prep<<<BAR_GRID, TB>>>(ei, p_ecc1, p_ctc1, p_ctr1);
    k_gather_t<true,false,false><<<G_NW1, TB>>>(p_t, p_g, p_offc, p_nbrc, p_ecc1,
                                                nullptr, nullptr, 0, p_act0, K1);
    k_gemm<<<G_G1, TB>>>(p_g, Wd + (size_t)3*DD*DD, bd + 3*DD, p_t,
                         nullptr, p_act0, K1);
    // d1 must be dense-valid (read as dense addin later) -> full gather
    k_gather_t<true,false,false><<<G_NW, TB>>>(p_t, p_d1, p_offc, p_nbrc, p_ecc1,
                                               nullptr, nullptr, 0, nullptr, NN);
    k_gather_t<true,false,true><<<G_NW1, TB>>>(p_d1, p_h, p_offc, p_nbrc, p_ctc1,
                                               nullptr, pvec + DD, 1, p_act0, K1);
    k_keys<<<G_N, TB>>>(K2);
    k_scanp<<<SCAN_GRID, 256>>>();
    for (int p = 1; p < 3; p++) { k_count<<<G_N, TB>>>(p); k_scanp<<<SCAN_GRID, 256>>>(); }
    k_applynode<<<G_N, TB>>>(p_act1, p_acnt1);

    // ---- bottom ----
    k_gemm<<<G_G2, TB>>>(p_h, Wb, bb, p_t, p_s, p_act1, K2);
    k_prep<<<BAR_GRID, TB>>>(ei, p_ecc2, nullptr, nullptr);
    k_gather_t<true,false,false><<<G_NW2, TB>>>(p_t, p_g, p_offc, p_nbrc, p_ecc2,
                                                nullptr, nullptr, 0, p_act1, K2);
    k_gemm<<<G_G2, TB>>>(p_g, Wb + (size_t)1*DD*DD, bb + 1*DD, p_t,
                         nullptr, p_act1, K2);
    // x must be valid for all act0 nodes (read by ctr1 gather) -> act0 list
    k_gather_t<true,false,false><<<G_NW1, TB>>>(p_t, p_x, p_offc, p_nbrc, p_ecc2,
                                                nullptr, nullptr, 0, p_act0, K1);

    // ---- up level 0 (act0 domain) ----
    k_gather_t<true,false,false><<<G_NW1, TB>>>(p_x, p_h, p_offr, p_nbrr, p_ctr1,
                                                nullptr, nullptr, 0, p_act0, K1);
    k_gemm<<<G_G1, TB>>>(p_h, Wu, bu, p_t, nullptr, p_act0, K1);
    k_gather_t<true,false,false><<<G_NW1, TB>>>(p_t, p_g, p_offc, p_nbrc, p_ecc1,
                                                nullptr, nullptr, 0, p_act0, K1);
    k_gemm<<<G_G1, TB>>>(p_g, Wu + (size_t)1*DD*DD, bu + 1*DD, p_t,
                         nullptr, p_act0, K1);
    // x = gather + d1 must be dense-valid (read by dense ctr0 gather) -> full
    k_gather_t<true,true,false><<<G_NW, TB>>>(p_t, p_x, p_offc, p_nbrc, p_ecc1,
                                              p_d1, nullptr, 0, nullptr, NN);

    // ---- up level 1 (dense, full graph) ----
    k_gather_t<false,false,false><<<G_NW, TB>>>(p_x, p_h, p_offr, p_nbrr, p_ctr0,
                                                nullptr, nullptr, 0, nullptr, NN);
    k_gemm<<<G_GF, TB>>>(p_h, Wu + (size_t)2*DD*DD, bu + 2*DD, p_t,
                         nullptr, nullptr, NN);
    k_gather_t<false,false,false><<<G_NW, TB>>>(p_t, p_g, p_offc, p_nbrc, p_ecc0,
                                                nullptr, nullptr, 0, nullptr, NN);
    k_gemm<<<G_GF, TB>>>(p_g, Wu + (size_t)3*DD*DD, bu + 3*DD, p_t,
                         nullptr, nullptr, NN);
    k_gather_t<false,true,false><<<G_NW, TB>>>(p_t, out, p_offc, p_nbrc, p_ecc0,
                                               p_d0, nullptr, 0, nullptr, NN);
}